// round 5
// baseline (speedup 1.0000x reference)
#include <cuda_runtime.h>
#include <cuda_bf16.h>
#include <math.h>

// LRML memory-network scoring — smem-transpose, thread-per-element compute.
//  0: user_ids  int32  [B]
//  1: item_ids  int32  [B]
//  2: user_emb  f32    [U, 32]
//  3: item_emb  f32    [I, 32]
//  4: W_att     f32    [10, 32]
//  5: memory    f32    [10, 32]
// Output: f32 [B] = -sum((ue + rel - ie)^2)
//
// Phase 1: coalesced gather of 128 rows (64 user + 64 item) into shared
//          memory, 8 lanes per row, row stride 144B (== 16 mod 128) so
//          phase-2 per-thread float4 reads are bank-conflict-free.
// Phase 2: thread t computes element t start-to-finish: zero shuffles,
//          softmax once per element, everything register-resident.

#define M 10
#define EPB 64                 // elements per block == threads per block
#define ROW_STRIDE 36          // floats per row slot (144 bytes)

__global__ __launch_bounds__(EPB)
void LRML_90804198572513_kernel(const int* __restrict__ user_ids,
                                const int* __restrict__ item_ids,
                                const float* __restrict__ user_emb,
                                const float* __restrict__ item_emb,
                                const float* __restrict__ W_att,
                                const float* __restrict__ memory,
                                float* __restrict__ out,
                                int B) {
    __shared__ __align__(16) float rows[2 * EPB * ROW_STRIDE]; // u rows then i rows
    __shared__ __align__(16) float4 sW[M * 8];                 // W_att
    __shared__ __align__(16) float4 sM[M * 8];                 // memory
    __shared__ int sids[2 * EPB];

    const int tid  = threadIdx.x;
    const int base = blockIdx.x * EPB;
    const int b    = base + tid;

    // --- Stage ids and the tiny parameter matrices ---
    sids[tid]       = user_ids[b];
    sids[EPB + tid] = item_ids[b];
    for (int i = tid; i < M * 8; i += EPB) {
        sW[i] = ((const float4*)W_att)[i];
        sM[i] = ((const float4*)memory)[i];
    }
    __syncthreads();

    // --- Phase 1: coalesced row gather ---
    // 128 rows x 8 float4 = 1024 float4, 16 per thread. Consecutive lanes
    // cover consecutive float4s, so 8-lane groups read full 128B rows.
    #pragma unroll
    for (int c = 0; c < 16; c++) {
        const int g   = c * EPB + tid;
        const int row = g >> 3;          // 0..127
        const int sub = g & 7;           // float4 index within row
        const float* tab = (row < EPB) ? user_emb : item_emb;
        const size_t id = (size_t)sids[row];
        const float4 v = ((const float4*)(tab + id * 32))[sub];
        *(float4*)&rows[row * ROW_STRIDE + sub * 4] = v;
    }
    __syncthreads();

    // --- Phase 2: thread t owns element t ---
    const float* urow = &rows[tid * ROW_STRIDE];
    const float* irow = &rows[(EPB + tid) * ROW_STRIDE];

    // Load both rows into registers; accumulate norms and unscaled scores.
    float4 u[8], iv[8];
    float nu = 0.0f, ni = 0.0f;
    float s[M];
    #pragma unroll
    for (int m = 0; m < M; m++) s[m] = 0.0f;

    #pragma unroll
    for (int k = 0; k < 8; k++) {
        u[k]  = *(const float4*)&urow[k * 4];
        iv[k] = *(const float4*)&irow[k * 4];
        nu = fmaf(u[k].x, u[k].x, nu);  nu = fmaf(u[k].y, u[k].y, nu);
        nu = fmaf(u[k].z, u[k].z, nu);  nu = fmaf(u[k].w, u[k].w, nu);
        ni = fmaf(iv[k].x, iv[k].x, ni); ni = fmaf(iv[k].y, iv[k].y, ni);
        ni = fmaf(iv[k].z, iv[k].z, ni); ni = fmaf(iv[k].w, iv[k].w, ni);
        // unscaled joint chunk
        float4 j;
        j.x = u[k].x * iv[k].x; j.y = u[k].y * iv[k].y;
        j.z = u[k].z * iv[k].z; j.w = u[k].w * iv[k].w;
        #pragma unroll
        for (int m = 0; m < M; m++) {
            const float4 w = sW[m * 8 + k];   // broadcast LDS
            s[m] = fmaf(j.x, w.x, s[m]); s[m] = fmaf(j.y, w.y, s[m]);
            s[m] = fmaf(j.z, w.z, s[m]); s[m] = fmaf(j.w, w.w, s[m]);
        }
    }

    // scale = 1/max(||e||,1) = min(rsqrt(n),1)  (n=0 -> inf -> 1, fine)
    const float su = fminf(rsqrtf(nu), 1.0f);
    const float si = fminf(rsqrtf(ni), 1.0f);
    const float sj = su * si;

    // Softmax over M=10 (once per element).
    float mx = s[0] * sj;
    #pragma unroll
    for (int m = 0; m < M; m++) { s[m] *= sj; mx = fmaxf(mx, s[m]); }
    float sum = 0.0f;
    #pragma unroll
    for (int m = 0; m < M; m++) { s[m] = __expf(s[m] - mx); sum += s[m]; }
    const float inv = 1.0f / sum;
    #pragma unroll
    for (int m = 0; m < M; m++) s[m] *= inv;   // p[m]

    // rel chunk-by-chunk, immediately consumed into the distance.
    float d = 0.0f;
    #pragma unroll
    for (int k = 0; k < 8; k++) {
        float4 r = make_float4(0.f, 0.f, 0.f, 0.f);
        #pragma unroll
        for (int m = 0; m < M; m++) {
            const float4 mm = sM[m * 8 + k];  // broadcast LDS
            r.x = fmaf(s[m], mm.x, r.x); r.y = fmaf(s[m], mm.y, r.y);
            r.z = fmaf(s[m], mm.z, r.z); r.w = fmaf(s[m], mm.w, r.w);
        }
        float dx;
        dx = fmaf(su, u[k].x, r.x) - si * iv[k].x; d = fmaf(dx, dx, d);
        dx = fmaf(su, u[k].y, r.y) - si * iv[k].y; d = fmaf(dx, dx, d);
        dx = fmaf(su, u[k].z, r.z) - si * iv[k].z; d = fmaf(dx, dx, d);
        dx = fmaf(su, u[k].w, r.w) - si * iv[k].w; d = fmaf(dx, dx, d);
    }

    out[b] = -d;
}

extern "C" void kernel_launch(void* const* d_in, const int* in_sizes, int n_in,
                              void* d_out, int out_size) {
    const int*   user_ids = (const int*)  d_in[0];
    const int*   item_ids = (const int*)  d_in[1];
    const float* user_emb = (const float*)d_in[2];
    const float* item_emb = (const float*)d_in[3];
    const float* W_att    = (const float*)d_in[4];
    const float* memory   = (const float*)d_in[5];
    float* out = (float*)d_out;

    const int B = in_sizes[0];
    const int grid = (B + EPB - 1) / EPB;   // B=16384 -> 256 blocks
    LRML_90804198572513_kernel<<<grid, EPB>>>(
        user_ids, item_ids, user_emb, item_emb, W_att, memory, out, B);
}

// round 6
// speedup vs baseline: 1.6381x; 1.6381x over previous
#include <cuda_runtime.h>
#include <cuda_bf16.h>
#include <math.h>

// LRML memory-network scoring — G=8 lanes/element + packed f32x2 math.
//  0: user_ids  int32  [B]
//  1: item_ids  int32  [B]
//  2: user_emb  f32    [U, 32]
//  3: item_emb  f32    [I, 32]
//  4: W_att     f32    [10, 32]
//  5: memory    f32    [10, 32]
// Output: f32 [B] = -sum((ue + rel - ie)^2)
//
// Lane `sub` (0..7) owns dims [4*sub, 4*sub+4) as one ulonglong2
// (= two f32x2 packed pairs). One warp covers 4 elements; 4096 warps total.

#define M 10
#define TPB 128               // 4 warps -> 16 elements per block

typedef unsigned long long u64t;

__device__ __forceinline__ u64t fma2(u64t a, u64t b, u64t c) {
    u64t d;
    asm("fma.rn.f32x2 %0, %1, %2, %3;" : "=l"(d) : "l"(a), "l"(b), "l"(c));
    return d;
}
__device__ __forceinline__ u64t mul2(u64t a, u64t b) {
    u64t d;
    asm("mul.rn.f32x2 %0, %1, %2;" : "=l"(d) : "l"(a), "l"(b));
    return d;
}
__device__ __forceinline__ u64t pack2(float lo, float hi) {
    u64t d;
    asm("mov.b64 %0, {%1, %2};" : "=l"(d) : "f"(lo), "f"(hi));
    return d;
}
__device__ __forceinline__ float hadd2(u64t a) {   // lo + hi
    float x, y;
    asm("mov.b64 {%0, %1}, %2;" : "=f"(x), "=f"(y) : "l"(a));
    return x + y;
}
__device__ __forceinline__ float ex2a(float x) {   // 2^x, MUFU
    float y;
    asm("ex2.approx.f32 %0, %1;" : "=f"(y) : "f"(x));
    return y;
}
__device__ __forceinline__ float rcpa(float x) {   // 1/x, MUFU
    float y;
    asm("rcp.approx.f32 %0, %1;" : "=f"(y) : "f"(x));
    return y;
}

__global__ __launch_bounds__(TPB)
void LRML_90804198572513_kernel(const int* __restrict__ user_ids,
                                const int* __restrict__ item_ids,
                                const float* __restrict__ user_emb,
                                const float* __restrict__ item_emb,
                                const float* __restrict__ W_att,
                                const float* __restrict__ memory,
                                float* __restrict__ out,
                                int B) {
    __shared__ __align__(16) ulonglong2 sW[M * 8];  // W_att rows, 8 x 16B per row
    __shared__ __align__(16) ulonglong2 sM[M * 8];  // memory rows

    const int tid  = threadIdx.x;
    const int lane = tid & 31;
    const int warp = tid >> 5;
    const int sub  = lane & 7;        // dim-slice owner (0..7)
    const int eg   = lane >> 3;       // element within warp (0..3)
    const int b = ((blockIdx.x * (TPB / 32) + warp) << 2) + eg;
    const int bb = (b < B) ? b : (B - 1);

    // 1) ids (dependent DRAM load — issue first)
    const int uid = user_ids[bb];
    const int iid = item_ids[bb];

    // 2) stage parameter matrices (independent loads; overlap id latency)
    ulonglong2 wreg, mreg;
    const bool stager = (tid < M * 8);
    if (stager) {
        wreg = ((const ulonglong2*)W_att)[tid];
        mreg = ((const ulonglong2*)memory)[tid];
    }

    // 3) row gathers (dependent on ids). Lanes 0..7 cover a full 128B row.
    const ulonglong2 u  = ((const ulonglong2*)(user_emb + (size_t)uid * 32))[sub];
    const ulonglong2 iv = ((const ulonglong2*)(item_emb + (size_t)iid * 32))[sub];

    if (stager) { sW[tid] = wreg; sM[tid] = mreg; }
    __syncthreads();

    // 4) per-lane partials: norms + unscaled scores (packed math)
    const float nu = hadd2(fma2(u.y,  u.y,  mul2(u.x,  u.x)));
    const float ni = hadd2(fma2(iv.y, iv.y, mul2(iv.x, iv.x)));

    const u64t j0 = mul2(u.x, iv.x);   // unscaled joint (scale applied later)
    const u64t j1 = mul2(u.y, iv.y);

    float red[2 + M];
    red[0] = nu; red[1] = ni;
    #pragma unroll
    for (int m = 0; m < M; m++) {
        const ulonglong2 w = sW[m * 8 + sub];
        red[2 + m] = hadd2(fma2(j1, w.y, mul2(j0, w.x)));
    }

    // 5) one merged 3-stage butterfly over the 8-lane group (12 values, pipelined)
    #pragma unroll
    for (int o = 1; o <= 4; o <<= 1) {
        #pragma unroll
        for (int k = 0; k < 2 + M; k++)
            red[k] += __shfl_xor_sync(0xFFFFFFFFu, red[k], o);
    }

    // 6) scales; fold renorm product and log2(e) into one exp multiplier.
    //    scale = 1/max(||e||,1) = min(rsqrt(n),1)   (n=0 -> inf -> 1, fine)
    const float su  = fminf(rsqrtf(red[0]), 1.0f);
    const float si  = fminf(rsqrtf(red[1]), 1.0f);
    const float sjE = su * si * 1.44269504f;

    // 7) softmax without max-subtraction (|score| <~ 4, fp32-safe)
    float e[M], sum = 0.0f;
    #pragma unroll
    for (int m = 0; m < M; m++) { e[m] = ex2a(red[2 + m] * sjE); sum += e[m]; }
    const float inv = rcpa(sum);

    // 8) unnormalized rel for this lane's 4 dims (packed FMAs)
    u64t r0 = 0ull, r1 = 0ull;
    #pragma unroll
    for (int m = 0; m < M; m++) {
        const ulonglong2 mm = sM[m * 8 + sub];
        const u64t pp = pack2(e[m], e[m]);
        r0 = fma2(pp, mm.x, r0);
        r1 = fma2(pp, mm.y, r1);
    }

    // 9) dist: dx = su*u + inv*r - si*i, packed; then horizontal + group reduce
    const u64t su2  = pack2(su, su);
    const u64t nsi2 = pack2(-si, -si);
    const u64t inv2 = pack2(inv, inv);
    const u64t dx0 = fma2(su2, u.x, fma2(nsi2, iv.x, mul2(inv2, r0)));
    const u64t dx1 = fma2(su2, u.y, fma2(nsi2, iv.y, mul2(inv2, r1)));
    float d = hadd2(fma2(dx1, dx1, mul2(dx0, dx0)));
    d += __shfl_xor_sync(0xFFFFFFFFu, d, 1);
    d += __shfl_xor_sync(0xFFFFFFFFu, d, 2);
    d += __shfl_xor_sync(0xFFFFFFFFu, d, 4);

    if (sub == 0 && b < B) out[b] = -d;
}

extern "C" void kernel_launch(void* const* d_in, const int* in_sizes, int n_in,
                              void* d_out, int out_size) {
    const int*   user_ids = (const int*)  d_in[0];
    const int*   item_ids = (const int*)  d_in[1];
    const float* user_emb = (const float*)d_in[2];
    const float* item_emb = (const float*)d_in[3];
    const float* W_att    = (const float*)d_in[4];
    const float* memory   = (const float*)d_in[5];
    float* out = (float*)d_out;

    const int B = in_sizes[0];
    const int elems_per_block = (TPB / 32) * 4;  // 16
    const int grid = (B + elems_per_block - 1) / elems_per_block;
    LRML_90804198572513_kernel<<<grid, TPB>>>(
        user_ids, item_ids, user_emb, item_emb, W_att, memory, out, B);
}